// round 1
// baseline (speedup 1.0000x reference)
#include <cuda_runtime.h>
#include <math.h>

// Problem constants (fixed by setup_inputs)
#define D        64
#define NC       16
#define NS       136
#define NITEMS   5120        // 512 * 10
#define TPB      256
#define WPB      8           // warps per block
#define NB       (NITEMS / WPB)  // 640 blocks, 1 item per warp

__device__ double g_partial[NB];

__global__ __launch_bounds__(TPB)
void latent_main(const float* __restrict__ z, const float* __restrict__ mu,
                 const float* __restrict__ pi, const int* __restrict__ A,
                 const int* __restrict__ B) {
    __shared__ float  s_mu[D * NC];        // [d][c] layout (as in gmem)
    __shared__ float  s_invsig[NS], s_cab[NS], s_gbb[NS], s_lpi[NS];
    __shared__ int    s_A[NS], s_B[NS];
    __shared__ float  s_dz[WPB][NC];
    __shared__ float  s_z[WPB][D];
    __shared__ float  s_red[TPB];
    __shared__ double s_wsum[WPB];

    const float LOG2PI = 1.8378770664093453f;
    const float BASE   = -32.0f * LOG2PI;   // -0.5 * d * log(2pi), d=64

    int t = threadIdx.x;

    // ---- prelude: stage mu, A, B, pi ----
    #pragma unroll
    for (int i = t; i < D * NC; i += TPB) s_mu[i] = mu[i];
    float piv = -INFINITY;
    if (t < NS) { s_A[t] = A[t]; s_B[t] = B[t]; piv = pi[t]; }
    s_red[t] = piv;
    __syncthreads();

    // per-state constants (diff-form => diagonal states give EXACT 0)
    if (t < NS) {
        int a = s_A[t], b = s_B[t];
        float is = 0.f, cab = 0.f, gbb = 0.f;
        #pragma unroll
        for (int d = 0; d < D; d++) {
            float ma = s_mu[d * NC + a];
            float mb = s_mu[d * NC + b];
            float df = mb - ma;
            is  = fmaf(df, df, is);
            cab = fmaf(df, mb, cab);
            gbb = fmaf(mb, mb, gbb);
        }
        s_invsig[t] = is; s_cab[t] = cab; s_gbb[t] = gbb;
    }

    // softmax(pi): block max reduce
    for (int off = TPB / 2; off > 0; off >>= 1) {
        if (t < off) s_red[t] = fmaxf(s_red[t], s_red[t + off]);
        __syncthreads();
    }
    float pmax = s_red[0];
    __syncthreads();
    s_red[t] = (t < NS) ? expf(piv - pmax) : 0.f;
    __syncthreads();
    for (int off = TPB / 2; off > 0; off >>= 1) {
        if (t < off) s_red[t] += s_red[t + off];
        __syncthreads();
    }
    float psum = s_red[0];
    if (t < NS) s_lpi[t] = logf(expf(piv - pmax) / psum + 1e-12f);
    __syncthreads();

    // ---- one (b,l) item per warp ----
    int w = t >> 5, lane = t & 31;
    int item = blockIdx.x * WPB + w;   // [0, 5120)

    const float* zp = z + item * D;
    float z0 = zp[2 * lane];
    float z1 = zp[2 * lane + 1];
    s_z[w][2 * lane]     = z0;
    s_z[w][2 * lane + 1] = z1;

    // |z|^2 via butterfly (all lanes end with total)
    float zn = fmaf(z0, z0, z1 * z1);
    #pragma unroll
    for (int off = 16; off; off >>= 1)
        zn += __shfl_xor_sync(0xffffffffu, zn, off);

    __syncwarp();
    // lanes 0..15: dz[c] = <z, mu[:,c]>  (s_mu bank = lane -> conflict-free)
    if (lane < NC) {
        float dz = 0.f;
        #pragma unroll
        for (int d = 0; d < D; d++)
            dz = fmaf(s_z[w][d], s_mu[d * NC + lane], dz);
        s_dz[w][lane] = dz;
    }
    __syncwarp();

    // ---- 136 states striped over 32 lanes, online logsumexp ----
    float m = -1e30f, acc = 0.f;
    #pragma unroll
    for (int k = 0; k < 5; k++) {
        int s = lane + 32 * k;
        if (s < NS) {
            int a = s_A[s], b = s_B[s];
            float dzB    = s_dz[w][b];
            float invsig = s_invsig[s];
            float sq_a2  = zn - 2.f * dzB + s_gbb[s];
            float val;
            if (invsig == 0.f) {
                val = BASE + s_lpi[s] - 0.5f * sq_a2;
            } else {
                float dzA   = s_dz[w][a];
                float dot12 = (dzB - dzA) - s_cab[s];
                float mu_   = -dot12 / invsig;
                float tt    = fmaf(mu_ * mu_, invsig, -sq_a2);
                float sd    = sqrtf(invsig + 1e-12f);
                float cdfd  = normcdff((1.f - mu_) * sd) - normcdff(-mu_ * sd);
                val = BASE + s_lpi[s]
                    + 0.5f * (LOG2PI - logf(invsig + 1e-12f) + tt)
                    + logf(cdfd + 1e-12f);
            }
            if (val > m) { acc = acc * expf(m - val) + 1.f; m = val; }
            else         { acc += expf(val - m); }
        }
    }

    // warp-combine (m, acc) pairs
    #pragma unroll
    for (int off = 16; off; off >>= 1) {
        float m2 = __shfl_xor_sync(0xffffffffu, m,   off);
        float a2 = __shfl_xor_sync(0xffffffffu, acc, off);
        float M  = fmaxf(m, m2);
        acc = acc * expf(m - M) + a2 * expf(m2 - M);
        m = M;
    }
    float lse = m + logf(acc);

    if (lane == 0) s_wsum[w] = (double)lse;
    __syncthreads();
    if (t == 0) {
        double ssum = 0.0;
        #pragma unroll
        for (int i = 0; i < WPB; i++) ssum += s_wsum[i];
        g_partial[blockIdx.x] = ssum;
    }
}

__global__ __launch_bounds__(256)
void latent_finalize(float* __restrict__ out) {
    __shared__ double sr[256];
    int t = threadIdx.x;
    double v = 0.0;
    for (int i = t; i < NB; i += 256) v += g_partial[i];
    sr[t] = v;
    __syncthreads();
    for (int off = 128; off > 0; off >>= 1) {
        if (t < off) sr[t] += sr[t + off];
        __syncthreads();
    }
    if (t == 0) out[0] = (float)(sr[0] / (double)NITEMS);
}

extern "C" void kernel_launch(void* const* d_in, const int* in_sizes, int n_in,
                              void* d_out, int out_size) {
    const float* z  = (const float*)d_in[0];
    const float* mu = (const float*)d_in[1];
    const float* pi = (const float*)d_in[2];
    const int*   A  = (const int*)d_in[3];
    const int*   B  = (const int*)d_in[4];
    float* out = (float*)d_out;
    (void)in_sizes; (void)n_in; (void)out_size;

    latent_main<<<NB, TPB>>>(z, mu, pi, A, B);
    latent_finalize<<<1, 256>>>(out);
}